// round 10
// baseline (speedup 1.0000x reference)
#include <cuda_runtime.h>
#include <cstdint>

// Problem constants
namespace {
constexpr int kB   = 2;
constexpr int kS   = 2048;
constexpr int kDin = 2048;
constexpr int kNH  = 32;
constexpr int kNKV = 8;
constexpr int kHD  = 64;
constexpr int kDout = 2048;           // kNH * kHD
constexpr int kM   = kB * kS;         // 4096 rows
constexpr int kKV  = kNKV * kHD;      // 512
// combined scale: (1/sqrt(64)) * log2(e) so softmax uses raw EX2
constexpr float kQScale = 0.18033688f;
}

// Scratch (static device arrays; cudaMalloc is forbidden)
__device__ float g_Q[kM * kDout];       // 32 MB (pre-scaled, tf32-rounded, [b,h,s,d])
__device__ float g_Kr[kM * kKV];        // 8 MB (tf32-rounded, [b,g,s,d])
__device__ float g_Vr[kM * kKV];        // 8 MB (tf32-rounded, [b,g,s,d])
__device__ float g_Ctx[kM * kDout];     // 32 MB (tf32-rounded)
__device__ float g_xr[kM * kDin];       // 32 MB (tf32-rounded inputs/weights)
__device__ float g_Wqr[kDout * kDin];   // 16 MB
__device__ float g_Wkr[kKV * kDin];     // 4 MB
__device__ float g_Wvr[kKV * kDin];     // 4 MB
__device__ float g_Wor[kDin * kDout];   // 16 MB

__device__ __forceinline__ uint32_t f2tf32(float f) {
  uint32_t u;
  asm("cvt.rna.tf32.f32 %0, %1;" : "=r"(u) : "f"(f));
  return u;
}
__device__ __forceinline__ float rtf(float f) { return __uint_as_float(f2tf32(f)); }

__device__ __forceinline__ float fexp2(float x) {
  float y;
  asm("ex2.approx.ftz.f32 %0, %1;" : "=f"(y) : "f"(x));
  return y;
}

__device__ __forceinline__ void cp_async16(uint32_t smem_addr, const void* gptr) {
  asm volatile("cp.async.cg.shared.global [%0], [%1], 16;" :: "r"(smem_addr), "l"(gptr));
}

__device__ __forceinline__ void mma_tf32(float* c, const uint32_t* a, const uint32_t* b) {
  asm volatile(
      "mma.sync.aligned.m16n8k8.row.col.f32.tf32.tf32.f32 "
      "{%0,%1,%2,%3}, {%4,%5,%6,%7}, {%8,%9}, {%0,%1,%2,%3};"
      : "+f"(c[0]), "+f"(c[1]), "+f"(c[2]), "+f"(c[3])
      : "r"(a[0]), "r"(a[1]), "r"(a[2]), "r"(a[3]), "r"(b[0]), "r"(b[1]));
}

// ---------------------------------------------------------------------------
// Pre-round all GEMM operands to TF32 in one streaming launch.
// ---------------------------------------------------------------------------
__global__ __launch_bounds__(256) void round5(
    const float4* __restrict__ x,  float4* __restrict__ xr,  int n0,
    const float4* __restrict__ wq, float4* __restrict__ wqr, int n1,
    const float4* __restrict__ wk, float4* __restrict__ wkr, int n2,
    const float4* __restrict__ wv, float4* __restrict__ wvr, int n3,
    const float4* __restrict__ wo, float4* __restrict__ wor, int n4) {
  int i = blockIdx.x * 256 + threadIdx.x;
  const float4* s; float4* d;
  if (i < n0) { s = x + i;  d = xr + i; }
  else if ((i -= n0) < n1) { s = wq + i; d = wqr + i; }
  else if ((i -= n1) < n2) { s = wk + i; d = wkr + i; }
  else if ((i -= n2) < n3) { s = wv + i; d = wvr + i; }
  else if ((i -= n3) < n4) { s = wo + i; d = wor + i; }
  else return;
  float4 v = *s;
  *d = make_float4(rtf(v.x), rtf(v.y), rtf(v.z), rtf(v.w));
}

// ---------------------------------------------------------------------------
// TF32 GEMM mainloop: 128x128x32, 3-stage cp.async pipeline, ONE barrier per
// iteration (stage-(it-1) compute is block-complete at the iteration-entry
// barrier, so the load into that buffer issued after it is hazard-free).
// Operands pre-rounded to tf32 -> fragment loads are raw uint LDS.
// ---------------------------------------------------------------------------
struct GemmCtx {
  int m0, wm0, wn0, lq, lr8;
};

template <typename Epi>
__device__ __forceinline__ void gemm_body(
    const float* __restrict__ A, const float* __restrict__ Bw,
    int K, float* smem, Epi&& epilogue) {
  constexpr int BM = 128, BN = 128, BK = 32, LD = 36, STG = 3;
  float* As = smem;                     // [STG][BM][LD]
  float* Bs = smem + STG * BM * LD;     // [STG][BN][LD]

  const int m0 = blockIdx.y * BM;
  const int t = threadIdx.x;
  const int lane = t & 31, w = t >> 5;
  const int wm0 = (w & 3) * 32;
  const int wn0 = (w >> 2) * 64;
  const int lq = lane & 3;
  const int lr8 = lane >> 2;
  const int grow = t >> 3;
  const int gk4  = (t & 7) * 4;

  const float* Agp = A  + (m0 + grow) * (long)K + gk4;
  const float* Bgp = Bw + grow * (long)K + gk4;   // n0 pre-applied by caller

  uint32_t sA = (uint32_t)__cvta_generic_to_shared(As);
  uint32_t sB = (uint32_t)__cvta_generic_to_shared(Bs);

  auto load_stage = [&](int buf, int k0) {
    uint32_t abase = sA + (uint32_t)(buf * BM * LD) * 4u;
    uint32_t bbase = sB + (uint32_t)(buf * BN * LD) * 4u;
#pragma unroll
    for (int s = 0; s < 4; s++) {
      int row = grow + s * 32;
      cp_async16(abase + (uint32_t)(row * LD + gk4) * 4u, Agp + (long)s * 32 * K + k0);
      cp_async16(bbase + (uint32_t)(row * LD + gk4) * 4u, Bgp + (long)s * 32 * K + k0);
    }
    asm volatile("cp.async.commit_group;" ::: "memory");
  };

  float c[2][8][4];
#pragma unroll
  for (int i = 0; i < 2; i++)
#pragma unroll
    for (int j = 0; j < 8; j++)
#pragma unroll
      for (int r = 0; r < 4; r++) c[i][j][r] = 0.f;

  const int NIT = K / BK;
  load_stage(0, 0);
  load_stage(1, BK);

  int buf = 0;
  for (int it = 0; it < NIT; it++) {
    // Oldest outstanding group (stage it) must be complete.
    if (it < NIT - 1) {
      asm volatile("cp.async.wait_group 1;" ::: "memory");
    } else {
      asm volatile("cp.async.wait_group 0;" ::: "memory");
    }
    __syncthreads();

    // Prefetch stage it+2 into the buffer freed by stage it-1 (hazard covered
    // by the barrier above), overlapping with this iteration's MMAs.
    if (it + 2 < NIT) {
      int nbuf = buf + 2;
      if (nbuf >= STG) nbuf -= STG;
      load_stage(nbuf, (it + 2) * BK);
    }

    const float* Ab = As + buf * BM * LD;
    const float* Bb = Bs + buf * BN * LD;

#pragma unroll
    for (int ks = 0; ks < 4; ks++) {
      const int kb = ks * 8;
      uint32_t af[2][4], bf[8][2];
#pragma unroll
      for (int mt = 0; mt < 2; mt++) {
        const uint32_t* ap = (const uint32_t*)(Ab + (wm0 + mt * 16 + lr8) * LD + kb + lq);
        af[mt][0] = ap[0];
        af[mt][1] = ap[8 * LD];
        af[mt][2] = ap[4];
        af[mt][3] = ap[8 * LD + 4];
      }
#pragma unroll
      for (int nt = 0; nt < 8; nt++) {
        const uint32_t* bp = (const uint32_t*)(Bb + (wn0 + nt * 8 + lr8) * LD + kb + lq);
        bf[nt][0] = bp[0];
        bf[nt][1] = bp[4];
      }
#pragma unroll
      for (int mt = 0; mt < 2; mt++)
#pragma unroll
        for (int nt = 0; nt < 8; nt++) mma_tf32(c[mt][nt], af[mt], bf[nt]);
    }

    if (++buf == STG) buf = 0;
  }

  GemmCtx ctx{m0, wm0, wn0, lq, lr8};
  epilogue(ctx, c);
}

// ---------------------------------------------------------------------------
// Fused Q/K/V projection. grid = (24, 32):
//   blockIdx.x  0..15 -> Q n-tile   epilogue: scale+round -> g_Q [b,h,s,d]
//   blockIdx.x 16..19 -> K n-tile   epilogue: keys exact + Kr rounded [b,g,s,d]
//   blockIdx.x 20..23 -> V n-tile   epilogue: values exact + Vr rounded
// ---------------------------------------------------------------------------
__global__ __launch_bounds__(256) void proj_qkv(
    const float* __restrict__ x, const float* __restrict__ Wq,
    const float* __restrict__ Wk, const float* __restrict__ Wv,
    float* __restrict__ Qo, float* __restrict__ keys, float* __restrict__ values,
    float* __restrict__ Kr, float* __restrict__ Vr) {
  extern __shared__ float smem[];
  const int bx = blockIdx.x;
  const float* Bw;
  int n0, which;
  if (bx < 16)      { Bw = Wq; n0 = bx * 128;        which = 0; }
  else if (bx < 20) { Bw = Wk; n0 = (bx - 16) * 128; which = 1; }
  else              { Bw = Wv; n0 = (bx - 20) * 128; which = 2; }

  gemm_body(x, Bw + (long)n0 * kDin, kDin, smem,
    [&](const GemmCtx& g, float c[2][8][4]) {
      float* ex = (which == 1) ? keys : values;
      float* rd = (which == 1) ? Kr : Vr;
#pragma unroll
      for (int mt = 0; mt < 2; mt++) {
        int mrow = g.m0 + g.wm0 + mt * 16 + g.lr8;
        int b = mrow >> 11, s = mrow & 2047;
#pragma unroll
        for (int nt = 0; nt < 8; nt++) {
          int coln = n0 + g.wn0 + nt * 8 + g.lq * 2;
          int head = coln >> 6, d = coln & 63;
          if (which == 0) {
            long dst = ((long)(b * kNH + head) * kS + s) * kHD + d;
            *(float2*)(Qo + dst) =
                make_float2(rtf(c[mt][nt][0] * kQScale), rtf(c[mt][nt][1] * kQScale));
            *(float2*)(Qo + dst + 8 * kHD) =
                make_float2(rtf(c[mt][nt][2] * kQScale), rtf(c[mt][nt][3] * kQScale));
          } else {
            long dst = ((long)(b * kNKV + head) * kS + s) * kHD + d;
            *(float2*)(ex + dst) = make_float2(c[mt][nt][0], c[mt][nt][1]);
            *(float2*)(ex + dst + 8 * kHD) = make_float2(c[mt][nt][2], c[mt][nt][3]);
            *(float2*)(rd + dst) = make_float2(rtf(c[mt][nt][0]), rtf(c[mt][nt][1]));
            *(float2*)(rd + dst + 8 * kHD) = make_float2(rtf(c[mt][nt][2]), rtf(c[mt][nt][3]));
          }
        }
      }
    });
}

// ---------------------------------------------------------------------------
// O-projection: out[M,N] = Ctx @ Wo^T (plain epilogue).
// ---------------------------------------------------------------------------
__global__ __launch_bounds__(256) void gemm_out(
    const float* __restrict__ A, const float* __restrict__ Bw,
    float* __restrict__ C, int N, int K) {
  extern __shared__ float smem[];
  const int n0 = blockIdx.x * 128;
  gemm_body(A, Bw + (long)n0 * K, K, smem,
    [&](const GemmCtx& g, float c[2][8][4]) {
#pragma unroll
      for (int mt = 0; mt < 2; mt++) {
        int mrow = g.m0 + g.wm0 + mt * 16 + g.lr8;
#pragma unroll
        for (int nt = 0; nt < 8; nt++) {
          int col = n0 + g.wn0 + nt * 8 + g.lq * 2;
          *(float2*)(C + (long)mrow * N + col) = make_float2(c[mt][nt][0], c[mt][nt][1]);
          *(float2*)(C + (long)(mrow + 8) * N + col) = make_float2(c[mt][nt][2], c[mt][nt][3]);
        }
      }
    });
}

// ---------------------------------------------------------------------------
// Flash attention, TF32 mma.sync, cp.async-pipelined K/V tiles (unchanged).
// ---------------------------------------------------------------------------
__global__ __launch_bounds__(128) void attn_tf32(
    const float* __restrict__ Q, const float* __restrict__ Kc,
    const float* __restrict__ Vc, float* __restrict__ Ctx) {
  constexpr int LD = 68, LDV = 72;
  extern __shared__ float sm[];
  float* Qs = sm;                   // [128][LD]
  float* Ks = Qs + 128 * LD;        // [64][LD]
  float* Vs = Ks + 64 * LD;         // [64][LDV]
  float* Ps = Vs + 64 * LDV;        // [128][LD]

  const int qt = gridDim.x - 1 - blockIdx.x;   // heavy blocks first
  const int hb = blockIdx.y;
  const int b = hb >> 5, h = hb & 31, g = h >> 2;
  const int t = threadIdx.x, lane = t & 31, w = t >> 5;
  const int wq0 = w * 32;
  const int lq = lane & 3, lr8 = lane >> 2;
  const int q0 = qt * 128;

  const float* Qbase = Q  + ((long)(b * kNH + h) * kS + q0) * kHD;
  const float* Kbase = Kc + (long)(b * kNKV + g) * kS * kHD;
  const float* Vbase = Vc + (long)(b * kNKV + g) * kS * kHD;

  const uint32_t sK = (uint32_t)__cvta_generic_to_shared(Ks);
  const uint32_t sV = (uint32_t)__cvta_generic_to_shared(Vs);

  auto issue_K = [&](int k0) {
#pragma unroll
    for (int i = 0; i < 8; i++) {
      int chunk = t + i * 128;
      int r = chunk >> 4, cc = chunk & 15;
      cp_async16(sK + (uint32_t)(r * LD + cc * 4) * 4u, Kbase + (long)(k0 + r) * kHD + cc * 4);
    }
    asm volatile("cp.async.commit_group;" ::: "memory");
  };
  auto issue_V = [&](int k0) {
#pragma unroll
    for (int i = 0; i < 8; i++) {
      int chunk = t + i * 128;
      int r = chunk >> 4, cc = chunk & 15;
      cp_async16(sV + (uint32_t)(r * LDV + cc * 4) * 4u, Vbase + (long)(k0 + r) * kHD + cc * 4);
    }
    asm volatile("cp.async.commit_group;" ::: "memory");
  };

  issue_K(0);
  issue_V(0);

  {  // Q tile: contiguous rows
    const float* qp = Qbase + (long)t * kHD;
    float* dst = Qs + t * LD;
#pragma unroll
    for (int i = 0; i < 16; i++) *(float4*)(dst + i * 4) = *(const float4*)(qp + i * 4);
  }

  float out[2][8][4];
#pragma unroll
  for (int mt = 0; mt < 2; mt++)
#pragma unroll
    for (int nt = 0; nt < 8; nt++)
#pragma unroll
      for (int r = 0; r < 4; r++) out[mt][nt][r] = 0.f;
  float mrow[2][2] = {{-1e30f, -1e30f}, {-1e30f, -1e30f}};
  float lrow[2][2] = {{0.f, 0.f}, {0.f, 0.f}};

  const int nkt = 2 * qt + 2;
  for (int kt = 0; kt < nkt; kt++) {
    const int k0 = kt * 64;

    asm volatile("cp.async.wait_group 1;" ::: "memory");
    __syncthreads();

    // S = Q K^T
    float sc[2][8][4];
#pragma unroll
    for (int mt = 0; mt < 2; mt++)
#pragma unroll
      for (int nt = 0; nt < 8; nt++)
#pragma unroll
        for (int r = 0; r < 4; r++) sc[mt][nt][r] = 0.f;

#pragma unroll
    for (int ks = 0; ks < 8; ks++) {
      const int kb = ks * 8;
      uint32_t af[2][4], bf[8][2];
#pragma unroll
      for (int mt = 0; mt < 2; mt++) {
        const uint32_t* ap = (const uint32_t*)(Qs + (wq0 + mt * 16 + lr8) * LD + kb + lq);
        af[mt][0] = ap[0];
        af[mt][1] = ap[8 * LD];
        af[mt][2] = ap[4];
        af[mt][3] = ap[8 * LD + 4];
      }
#pragma unroll
      for (int nt = 0; nt < 8; nt++) {
        const uint32_t* bp = (const uint32_t*)(Ks + (nt * 8 + lr8) * LD + kb + lq);
        bf[nt][0] = bp[0];
        bf[nt][1] = bp[4];
      }
#pragma unroll
      for (int mt = 0; mt < 2; mt++)
#pragma unroll
        for (int nt = 0; nt < 8; nt++) mma_tf32(sc[mt][nt], af[mt], bf[nt]);
    }

    asm volatile("cp.async.wait_group 0;" ::: "memory");
    __syncthreads();
    if (kt + 1 < nkt) issue_K(k0 + 64);

    if (k0 + 63 > q0 + wq0) {
#pragma unroll
      for (int mt = 0; mt < 2; mt++) {
        int r0 = q0 + wq0 + mt * 16 + lr8;
        int r1 = r0 + 8;
#pragma unroll
        for (int nt = 0; nt < 8; nt++) {
          int col = k0 + nt * 8 + 2 * lq;
          if (col > r0)     sc[mt][nt][0] = -1e30f;
          if (col + 1 > r0) sc[mt][nt][1] = -1e30f;
          if (col > r1)     sc[mt][nt][2] = -1e30f;
          if (col + 1 > r1) sc[mt][nt][3] = -1e30f;
        }
      }
    }

#pragma unroll
    for (int mt = 0; mt < 2; mt++) {
      float mx0 = -1e30f, mx1 = -1e30f;
#pragma unroll
      for (int nt = 0; nt < 8; nt++) {
        mx0 = fmaxf(mx0, fmaxf(sc[mt][nt][0], sc[mt][nt][1]));
        mx1 = fmaxf(mx1, fmaxf(sc[mt][nt][2], sc[mt][nt][3]));
      }
      mx0 = fmaxf(mx0, __shfl_xor_sync(0xffffffffu, mx0, 1));
      mx0 = fmaxf(mx0, __shfl_xor_sync(0xffffffffu, mx0, 2));
      mx1 = fmaxf(mx1, __shfl_xor_sync(0xffffffffu, mx1, 1));
      mx1 = fmaxf(mx1, __shfl_xor_sync(0xffffffffu, mx1, 2));

      float mn0 = fmaxf(mrow[mt][0], mx0);
      float mn1 = fmaxf(mrow[mt][1], mx1);
      float e0 = fexp2(mrow[mt][0] - mn0);
      float e1 = fexp2(mrow[mt][1] - mn1);
      mrow[mt][0] = mn0; mrow[mt][1] = mn1;

      float s0 = 0.f, s1 = 0.f;
      float* pr0 = Ps + (wq0 + mt * 16 + lr8) * LD + 2 * lq;
      float* pr1 = pr0 + 8 * LD;
#pragma unroll
      for (int nt = 0; nt < 8; nt++) {
        float p0 = rtf(fexp2(sc[mt][nt][0] - mn0));
        float p1 = rtf(fexp2(sc[mt][nt][1] - mn0));
        float p2 = rtf(fexp2(sc[mt][nt][2] - mn1));
        float p3 = rtf(fexp2(sc[mt][nt][3] - mn1));
        s0 += p0 + p1;
        s1 += p2 + p3;
        *(float2*)(pr0 + nt * 8) = make_float2(p0, p1);
        *(float2*)(pr1 + nt * 8) = make_float2(p2, p3);
      }
      s0 += __shfl_xor_sync(0xffffffffu, s0, 1);
      s0 += __shfl_xor_sync(0xffffffffu, s0, 2);
      s1 += __shfl_xor_sync(0xffffffffu, s1, 1);
      s1 += __shfl_xor_sync(0xffffffffu, s1, 2);
      lrow[mt][0] = lrow[mt][0] * e0 + s0;
      lrow[mt][1] = lrow[mt][1] * e1 + s1;
#pragma unroll
      for (int nt = 0; nt < 8; nt++) {
        out[mt][nt][0] *= e0; out[mt][nt][1] *= e0;
        out[mt][nt][2] *= e1; out[mt][nt][3] *= e1;
      }
    }
    __syncwarp();

    // out += P V
#pragma unroll
    for (int ks = 0; ks < 8; ks++) {
      const int kb = ks * 8;
      uint32_t af[2][4], bf[8][2];
#pragma unroll
      for (int mt = 0; mt < 2; mt++) {
        const uint32_t* ap = (const uint32_t*)(Ps + (wq0 + mt * 16 + lr8) * LD + kb + lq);
        af[mt][0] = ap[0];
        af[mt][1] = ap[8 * LD];
        af[mt][2] = ap[4];
        af[mt][3] = ap[8 * LD + 4];
      }
#pragma unroll
      for (int nt = 0; nt < 8; nt++) {
        const uint32_t* vp = (const uint32_t*)(Vs + (kb + lq) * LDV + nt * 8 + lr8);
        bf[nt][0] = vp[0];
        bf[nt][1] = vp[4 * LDV];
      }
#pragma unroll
      for (int mt = 0; mt < 2; mt++)
#pragma unroll
        for (int nt = 0; nt < 8; nt++) mma_tf32(out[mt][nt], af[mt], bf[nt]);
    }
    __syncthreads();
    if (kt + 1 < nkt) issue_V(k0 + 64);
  }

  // Epilogue: normalize, round to tf32, store ctx ([b*s, 2048] for O-proj)
  float* Cb = Ctx + (long)(b * kS + q0) * kDout + h * kHD;
#pragma unroll
  for (int mt = 0; mt < 2; mt++) {
    int r0 = wq0 + mt * 16 + lr8;
    float inv0 = 1.f / lrow[mt][0];
    float inv1 = 1.f / lrow[mt][1];
#pragma unroll
    for (int nt = 0; nt < 8; nt++) {
      int col = nt * 8 + 2 * lq;
      *(float2*)(Cb + (long)r0 * kDout + col) =
          make_float2(rtf(out[mt][nt][0] * inv0), rtf(out[mt][nt][1] * inv0));
      *(float2*)(Cb + (long)(r0 + 8) * kDout + col) =
          make_float2(rtf(out[mt][nt][2] * inv1), rtf(out[mt][nt][3] * inv1));
    }
  }
}

// ---------------------------------------------------------------------------
extern "C" void kernel_launch(void* const* d_in, const int* in_sizes, int n_in,
                              void* d_out, int out_size) {
  const float* x  = (const float*)d_in[0];
  const float* Wq = (const float*)d_in[1];
  const float* Wk = (const float*)d_in[2];
  const float* Wv = (const float*)d_in[3];
  const float* Wo = (const float*)d_in[4];

  float* out    = (float*)d_out;                    // [2,2048,2048]
  float* keys   = out + kM * kDout;                 // [2,8,2048,64]
  float* values = keys + kB * kNKV * kS * kHD;      // [2,8,2048,64]

  float *qb, *kr, *vr, *cb, *xr, *wqr, *wkr, *wvr, *wor;
  cudaGetSymbolAddress((void**)&qb, g_Q);
  cudaGetSymbolAddress((void**)&kr, g_Kr);
  cudaGetSymbolAddress((void**)&vr, g_Vr);
  cudaGetSymbolAddress((void**)&cb, g_Ctx);
  cudaGetSymbolAddress((void**)&xr, g_xr);
  cudaGetSymbolAddress((void**)&wqr, g_Wqr);
  cudaGetSymbolAddress((void**)&wkr, g_Wkr);
  cudaGetSymbolAddress((void**)&wvr, g_Wvr);
  cudaGetSymbolAddress((void**)&wor, g_Wor);

  constexpr int kGemmSmem = 3 * 2 * 128 * 36 * (int)sizeof(float);   // 110592 B
  constexpr int kAttnSmem =
      (128 * 68 + 64 * 68 + 64 * 72 + 128 * 68) * (int)sizeof(float);  // 105472 B
  static bool attr_set = false;
  if (!attr_set) {
    cudaFuncSetAttribute(proj_qkv, cudaFuncAttributeMaxDynamicSharedMemorySize, kGemmSmem);
    cudaFuncSetAttribute(gemm_out, cudaFuncAttributeMaxDynamicSharedMemorySize, kGemmSmem);
    cudaFuncSetAttribute(attn_tf32, cudaFuncAttributeMaxDynamicSharedMemorySize, kAttnSmem);
    attr_set = true;
  }

  // 0. Pre-round all GEMM operands to TF32 (numerics identical to in-loop cvt)
  constexpr int n0 = kM * kDin / 4;      // x
  constexpr int n1 = kDout * kDin / 4;   // Wq
  constexpr int n2 = kKV * kDin / 4;     // Wk
  constexpr int n3 = kKV * kDin / 4;     // Wv
  constexpr int n4 = kDin * kDout / 4;   // Wo
  constexpr int ntot = n0 + n1 + n2 + n3 + n4;
  round5<<<(ntot + 255) / 256, 256>>>(
      (const float4*)x,  (float4*)xr,  n0,
      (const float4*)Wq, (float4*)wqr, n1,
      (const float4*)Wk, (float4*)wkr, n2,
      (const float4*)Wv, (float4*)wvr, n3,
      (const float4*)Wo, (float4*)wor, n4);

  // 1. Fused Q/K/V projections
  proj_qkv<<<dim3(24, kM / 128), 256, kGemmSmem>>>(
      xr, wqr, wkr, wvr, qb, keys, values, kr, vr);
  // 2. Attention (TF32 tensor cores, cp.async pipelined)
  attn_tf32<<<dim3(kS / 128, kB * kNH), dim3(128), kAttnSmem>>>(qb, kr, vr, cb);
  // 3. Output projection
  gemm_out<<<dim3(kDout / 128, kM / 128), 256, kGemmSmem>>>(cb, wor, out, kDout, kDin);
}

// round 12
// speedup vs baseline: 1.6980x; 1.6980x over previous
#include <cuda_runtime.h>
#include <cuda_fp16.h>
#include <cstdint>

// Problem constants
namespace {
constexpr int kB   = 2;
constexpr int kS   = 2048;
constexpr int kDin = 2048;
constexpr int kNH  = 32;
constexpr int kNKV = 8;
constexpr int kHD  = 64;
constexpr int kDout = 2048;           // kNH * kHD
constexpr int kM   = kB * kS;         // 4096 rows
constexpr int kKV  = kNKV * kHD;      // 512
// combined scale: (1/sqrt(64)) * log2(e) so softmax uses raw EX2
constexpr float kQScale = 0.18033688f;
}

// Scratch (static device arrays; cudaMalloc is forbidden)
__device__ __half g_Q[kM * kDout];       // 16 MB (pre-scaled fp16, [b,h,s,d])
__device__ __half g_Kh[kM * kKV];        // 4 MB (fp16, [b,g,s,d])
__device__ __half g_Vh[kM * kKV];        // 4 MB (fp16, TRANSPOSED [b,g,d,s])
__device__ __half g_Ctx[kM * kDout];     // 16 MB (fp16)
__device__ __half g_xh[kM * kDin];       // 16 MB (fp16 inputs/weights)
__device__ __half g_Wqh[kDout * kDin];   // 8 MB
__device__ __half g_Wkh[kKV * kDin];     // 2 MB
__device__ __half g_Wvh[kKV * kDin];     // 2 MB
__device__ __half g_Woh[kDin * kDout];   // 8 MB

__device__ __forceinline__ float fexp2(float x) {
  float y;
  asm("ex2.approx.ftz.f32 %0, %1;" : "=f"(y) : "f"(x));
  return y;
}

__device__ __forceinline__ void cp_async16(uint32_t smem_addr, const void* gptr) {
  asm volatile("cp.async.cg.shared.global [%0], [%1], 16;" :: "r"(smem_addr), "l"(gptr));
}

// fp16 tensor-core MMA: m16n8k16, fp32 accumulate
__device__ __forceinline__ void mma_f16(float* c, const uint32_t* a, const uint32_t* b) {
  asm volatile(
      "mma.sync.aligned.m16n8k16.row.col.f32.f16.f16.f32 "
      "{%0,%1,%2,%3}, {%4,%5,%6,%7}, {%8,%9}, {%0,%1,%2,%3};"
      : "+f"(c[0]), "+f"(c[1]), "+f"(c[2]), "+f"(c[3])
      : "r"(a[0]), "r"(a[1]), "r"(a[2]), "r"(a[3]), "r"(b[0]), "r"(b[1]));
}

__device__ __forceinline__ uint32_t pack_h2(float a, float b) {
  __half2 h = __floats2half2_rn(a, b);
  return *(uint32_t*)&h;
}

// ---------------------------------------------------------------------------
// Cast all GEMM operands to fp16 in one streaming launch (float4 granularity).
// ---------------------------------------------------------------------------
__global__ __launch_bounds__(256) void half5(
    const float4* __restrict__ x,  uint2* __restrict__ xh,  int n0,
    const float4* __restrict__ wq, uint2* __restrict__ wqh, int n1,
    const float4* __restrict__ wk, uint2* __restrict__ wkh, int n2,
    const float4* __restrict__ wv, uint2* __restrict__ wvh, int n3,
    const float4* __restrict__ wo, uint2* __restrict__ woh, int n4) {
  int i = blockIdx.x * 256 + threadIdx.x;
  const float4* s; uint2* d;
  if (i < n0) { s = x + i;  d = xh + i; }
  else if ((i -= n0) < n1) { s = wq + i; d = wqh + i; }
  else if ((i -= n1) < n2) { s = wk + i; d = wkh + i; }
  else if ((i -= n2) < n3) { s = wv + i; d = wvh + i; }
  else if ((i -= n3) < n4) { s = wo + i; d = woh + i; }
  else return;
  float4 v = *s;
  *d = make_uint2(pack_h2(v.x, v.y), pack_h2(v.z, v.w));
}

// ---------------------------------------------------------------------------
// fp16 GEMM mainloop: 128x128x32, 2-stage cp.async double buffer.
// smem rows are LD=40 halves (conflict-free fragment loads: bank = 4*lr8+lq).
// ---------------------------------------------------------------------------
struct GemmCtx {
  int m0, wm0, wn0, lq, lr8;
};

template <typename Epi>
__device__ __forceinline__ void gemm_body(
    const __half* __restrict__ A, const __half* __restrict__ Bw,
    int K, char* smem, Epi&& epilogue) {
  constexpr int BM = 128, BN = 128, BK = 32, LD = 40;   // LD in halves
  __half* As = (__half*)smem;                 // [2][BM][LD]
  __half* Bs = As + 2 * BM * LD;              // [2][BN][LD]

  const int m0 = blockIdx.y * BM;
  const int t = threadIdx.x;
  const int lane = t & 31, w = t >> 5;
  const int wm0 = (w & 3) * 32;
  const int wn0 = (w >> 2) * 64;
  const int lq = lane & 3;
  const int lr8 = lane >> 2;
  // global loads: 512 16B-chunks per tile (128 rows x 4), 256 thr x 2
  const int r0c = t >> 2, c0c = (t & 3) * 8;         // chunk 0: row t>>2
  // chunk 1 = chunk 0 + 64 rows

  const __half* Agp = A  + (m0 + r0c) * (long)K + c0c;
  const __half* Bgp = Bw + r0c * (long)K + c0c;      // n0 pre-applied by caller

  uint32_t sA = (uint32_t)__cvta_generic_to_shared(As);
  uint32_t sB = (uint32_t)__cvta_generic_to_shared(Bs);

  auto load_stage = [&](int buf, int k0) {
    uint32_t abase = sA + (uint32_t)(buf * BM * LD) * 2u;
    uint32_t bbase = sB + (uint32_t)(buf * BN * LD) * 2u;
#pragma unroll
    for (int s = 0; s < 2; s++) {
      int row = r0c + s * 64;
      cp_async16(abase + (uint32_t)(row * LD + c0c) * 2u, Agp + (long)s * 64 * K + k0);
      cp_async16(bbase + (uint32_t)(row * LD + c0c) * 2u, Bgp + (long)s * 64 * K + k0);
    }
    asm volatile("cp.async.commit_group;" ::: "memory");
  };

  float c[2][8][4];
#pragma unroll
  for (int i = 0; i < 2; i++)
#pragma unroll
    for (int j = 0; j < 8; j++)
#pragma unroll
      for (int r = 0; r < 4; r++) c[i][j][r] = 0.f;

  const int NIT = K / BK;
  load_stage(0, 0);

  for (int it = 0; it < NIT; it++) {
    if (it + 1 < NIT) {
      load_stage((it + 1) & 1, (it + 1) * BK);
      asm volatile("cp.async.wait_group 1;" ::: "memory");
    } else {
      asm volatile("cp.async.wait_group 0;" ::: "memory");
    }
    __syncthreads();

    const uint32_t* Ab = (const uint32_t*)(As + (it & 1) * BM * LD);
    const uint32_t* Bb = (const uint32_t*)(Bs + (it & 1) * BN * LD);

#pragma unroll
    for (int ks = 0; ks < 2; ks++) {            // K=16 per step
      const int kh = ks * 8;                    // offset in half2 units
      uint32_t af[2][4], bf[8][2];
#pragma unroll
      for (int mt = 0; mt < 2; mt++) {
        const uint32_t* ap = Ab + (wm0 + mt * 16 + lr8) * (LD / 2) + kh + lq;
        af[mt][0] = ap[0];
        af[mt][1] = ap[8 * (LD / 2)];
        af[mt][2] = ap[4];
        af[mt][3] = ap[8 * (LD / 2) + 4];
      }
#pragma unroll
      for (int nt = 0; nt < 8; nt++) {
        const uint32_t* bp = Bb + (wn0 + nt * 8 + lr8) * (LD / 2) + kh + lq;
        bf[nt][0] = bp[0];
        bf[nt][1] = bp[4];
      }
#pragma unroll
      for (int mt = 0; mt < 2; mt++)
#pragma unroll
        for (int nt = 0; nt < 8; nt++) mma_f16(c[mt][nt], af[mt], bf[nt]);
    }
    __syncthreads();
  }

  GemmCtx ctx{m0, wm0, wn0, lq, lr8};
  epilogue(ctx, c);
}

// ---------------------------------------------------------------------------
// Fused Q/K/V projection. grid = (24, 32):
//   bx  0..15 -> Q n-tile   epilogue: scale -> g_Q fp16 [b,h,s,d]
//   bx 16..19 -> K n-tile   epilogue: keys fp32 + Kh fp16 [b,g,s,d]
//   bx 20..23 -> V n-tile   epilogue: values fp32 + Vh fp16 TRANSPOSED [b,g,d,s]
// ---------------------------------------------------------------------------
__global__ __launch_bounds__(256) void proj_qkv(
    const __half* __restrict__ x, const __half* __restrict__ Wq,
    const __half* __restrict__ Wk, const __half* __restrict__ Wv,
    __half* __restrict__ Qo, float* __restrict__ keys, float* __restrict__ values,
    __half* __restrict__ Kh, __half* __restrict__ Vh) {
  extern __shared__ char smem[];
  const int bx = blockIdx.x;
  const __half* Bw;
  int n0, which;
  if (bx < 16)      { Bw = Wq; n0 = bx * 128;        which = 0; }
  else if (bx < 20) { Bw = Wk; n0 = (bx - 16) * 128; which = 1; }
  else              { Bw = Wv; n0 = (bx - 20) * 128; which = 2; }

  gemm_body(x, Bw + (long)n0 * kDin, kDin, smem,
    [&](const GemmCtx& g, float c[2][8][4]) {
#pragma unroll
      for (int mt = 0; mt < 2; mt++) {
        int mrow = g.m0 + g.wm0 + mt * 16 + g.lr8;
        int b = mrow >> 11, s = mrow & 2047;
#pragma unroll
        for (int nt = 0; nt < 8; nt++) {
          int coln = n0 + g.wn0 + nt * 8 + g.lq * 2;
          int head = coln >> 6, d = coln & 63;
          if (which == 0) {
            long dst = ((long)(b * kNH + head) * kS + s) * kHD + d;
            *(uint32_t*)(Qo + dst) =
                pack_h2(c[mt][nt][0] * kQScale, c[mt][nt][1] * kQScale);
            *(uint32_t*)(Qo + dst + 8 * kHD) =
                pack_h2(c[mt][nt][2] * kQScale, c[mt][nt][3] * kQScale);
          } else if (which == 1) {
            long dst = ((long)(b * kNKV + head) * kS + s) * kHD + d;
            *(float2*)(keys + dst) = make_float2(c[mt][nt][0], c[mt][nt][1]);
            *(float2*)(keys + dst + 8 * kHD) = make_float2(c[mt][nt][2], c[mt][nt][3]);
            *(uint32_t*)(Kh + dst) = pack_h2(c[mt][nt][0], c[mt][nt][1]);
            *(uint32_t*)(Kh + dst + 8 * kHD) = pack_h2(c[mt][nt][2], c[mt][nt][3]);
          } else {
            long dst = ((long)(b * kNKV + head) * kS + s) * kHD + d;
            *(float2*)(values + dst) = make_float2(c[mt][nt][0], c[mt][nt][1]);
            *(float2*)(values + dst + 8 * kHD) = make_float2(c[mt][nt][2], c[mt][nt][3]);
            // transposed fp16 copy: [b,g,d,s]
            __half* vt = Vh + ((long)(b * kNKV + head) * kHD + d) * kS + s;
            vt[0]            = __float2half(c[mt][nt][0]);
            vt[kS]           = __float2half(c[mt][nt][1]);
            vt[8]            = __float2half(c[mt][nt][2]);
            vt[kS + 8]       = __float2half(c[mt][nt][3]);
          }
        }
      }
    });
}

// ---------------------------------------------------------------------------
// O-projection: out[M,N] = Ctx @ Wo^T (fp32 epilogue).
// ---------------------------------------------------------------------------
__global__ __launch_bounds__(256) void gemm_out(
    const __half* __restrict__ A, const __half* __restrict__ Bw,
    float* __restrict__ C, int N, int K) {
  extern __shared__ char smem[];
  const int n0 = blockIdx.x * 128;
  gemm_body(A, Bw + (long)n0 * K, K, smem,
    [&](const GemmCtx& g, float c[2][8][4]) {
#pragma unroll
      for (int mt = 0; mt < 2; mt++) {
        int mrow = g.m0 + g.wm0 + mt * 16 + g.lr8;
#pragma unroll
        for (int nt = 0; nt < 8; nt++) {
          int col = n0 + g.wn0 + nt * 8 + g.lq * 2;
          *(float2*)(C + (long)mrow * N + col) = make_float2(c[mt][nt][0], c[mt][nt][1]);
          *(float2*)(C + (long)(mrow + 8) * N + col) = make_float2(c[mt][nt][2], c[mt][nt][3]);
        }
      }
    });
}

// ---------------------------------------------------------------------------
// Flash attention, fp16 mma.sync m16n8k16, cp.async-pipelined K/V tiles.
// Q fp16 [b,h,s,d] (pre-scaled); K fp16 [b,g,s,d]; V fp16 TRANSPOSED [b,g,d,s].
// smem rows LD=72 halves (bank = 4*lr8+lq, conflict-free).
// ---------------------------------------------------------------------------
__global__ __launch_bounds__(128) void attn_f16(
    const __half* __restrict__ Q, const __half* __restrict__ Kc,
    const __half* __restrict__ Vt, __half* __restrict__ Ctx) {
  constexpr int LD = 72;                       // halves per row
  extern __shared__ char smraw[];
  __half* Qs = (__half*)smraw;                 // [128][LD] q rows, d cols
  __half* Ks = Qs + 128 * LD;                  // [64][LD]  k rows, d cols
  __half* Vs = Ks + 64 * LD;                   // [64][LD]  d rows, k cols (transposed)
  __half* Ps = Vs + 64 * LD;                   // [128][LD] q rows, k cols

  const int qt = gridDim.x - 1 - blockIdx.x;   // heavy blocks first
  const int hb = blockIdx.y;
  const int b = hb >> 5, h = hb & 31, g = h >> 2;
  const int t = threadIdx.x, lane = t & 31, w = t >> 5;
  const int wq0 = w * 32;
  const int lq = lane & 3, lr8 = lane >> 2;
  const int q0 = qt * 128;

  const __half* Qbase = Q  + ((long)(b * kNH + h) * kS + q0) * kHD;
  const __half* Kbase = Kc + (long)(b * kNKV + g) * kS * kHD;
  const __half* Vbase = Vt + (long)(b * kNKV + g) * kHD * kS;   // [d][s]

  const uint32_t sK = (uint32_t)__cvta_generic_to_shared(Ks);
  const uint32_t sV = (uint32_t)__cvta_generic_to_shared(Vs);

  // 64 rows x 64 halves = 512 16B-chunks per tile; 128 threads x 4
  auto issue_K = [&](int k0) {
#pragma unroll
    for (int i = 0; i < 4; i++) {
      int chunk = t + i * 128;
      int r = chunk >> 3, cc = (chunk & 7) * 8;
      cp_async16(sK + (uint32_t)(r * LD + cc) * 2u, Kbase + (long)(k0 + r) * kHD + cc);
    }
    asm volatile("cp.async.commit_group;" ::: "memory");
  };
  auto issue_V = [&](int k0) {
#pragma unroll
    for (int i = 0; i < 4; i++) {
      int chunk = t + i * 128;
      int r = chunk >> 3, cc = (chunk & 7) * 8;   // r = d row, cc = k col
      cp_async16(sV + (uint32_t)(r * LD + cc) * 2u, Vbase + (long)r * kS + k0 + cc);
    }
    asm volatile("cp.async.commit_group;" ::: "memory");
  };

  issue_K(0);
  issue_V(0);

  {  // Q tile: one contiguous 128B row per thread
    const uint4* qp = (const uint4*)(Qbase + (long)t * kHD);
    uint4* dst = (uint4*)(Qs + t * LD);
#pragma unroll
    for (int i = 0; i < 8; i++) dst[i] = qp[i];
  }

  float out[2][8][4];
#pragma unroll
  for (int mt = 0; mt < 2; mt++)
#pragma unroll
    for (int nt = 0; nt < 8; nt++)
#pragma unroll
      for (int r = 0; r < 4; r++) out[mt][nt][r] = 0.f;
  float mrow[2][2] = {{-1e30f, -1e30f}, {-1e30f, -1e30f}};
  float lrow[2][2] = {{0.f, 0.f}, {0.f, 0.f}};

  const uint32_t* Qs32 = (const uint32_t*)Qs;
  const uint32_t* Ks32 = (const uint32_t*)Ks;
  const uint32_t* Vs32 = (const uint32_t*)Vs;
  uint32_t* Ps32 = (uint32_t*)Ps;

  const int nkt = 2 * qt + 2;
  for (int kt = 0; kt < nkt; kt++) {
    const int k0 = kt * 64;

    asm volatile("cp.async.wait_group 1;" ::: "memory");
    __syncthreads();

    // S = Q K^T  (d = 64 -> 4 k16 steps)
    float sc[2][8][4];
#pragma unroll
    for (int mt = 0; mt < 2; mt++)
#pragma unroll
      for (int nt = 0; nt < 8; nt++)
#pragma unroll
        for (int r = 0; r < 4; r++) sc[mt][nt][r] = 0.f;

#pragma unroll
    for (int ks = 0; ks < 4; ks++) {
      const int kh = ks * 8;                       // half2 offset
      uint32_t af[2][4], bf[8][2];
#pragma unroll
      for (int mt = 0; mt < 2; mt++) {
        const uint32_t* ap = Qs32 + (wq0 + mt * 16 + lr8) * (LD / 2) + kh + lq;
        af[mt][0] = ap[0];
        af[mt][1] = ap[8 * (LD / 2)];
        af[mt][2] = ap[4];
        af[mt][3] = ap[8 * (LD / 2) + 4];
      }
#pragma unroll
      for (int nt = 0; nt < 8; nt++) {
        const uint32_t* bp = Ks32 + (nt * 8 + lr8) * (LD / 2) + kh + lq;
        bf[nt][0] = bp[0];
        bf[nt][1] = bp[4];
      }
#pragma unroll
      for (int mt = 0; mt < 2; mt++)
#pragma unroll
        for (int nt = 0; nt < 8; nt++) mma_f16(sc[mt][nt], af[mt], bf[nt]);
    }

    asm volatile("cp.async.wait_group 0;" ::: "memory");
    __syncthreads();
    if (kt + 1 < nkt) issue_K(k0 + 64);

    if (k0 + 63 > q0 + wq0) {
#pragma unroll
      for (int mt = 0; mt < 2; mt++) {
        int r0 = q0 + wq0 + mt * 16 + lr8;
        int r1 = r0 + 8;
#pragma unroll
        for (int nt = 0; nt < 8; nt++) {
          int col = k0 + nt * 8 + 2 * lq;
          if (col > r0)     sc[mt][nt][0] = -1e30f;
          if (col + 1 > r0) sc[mt][nt][1] = -1e30f;
          if (col > r1)     sc[mt][nt][2] = -1e30f;
          if (col + 1 > r1) sc[mt][nt][3] = -1e30f;
        }
      }
    }

    // Online softmax (log2 domain)
#pragma unroll
    for (int mt = 0; mt < 2; mt++) {
      float mx0 = -1e30f, mx1 = -1e30f;
#pragma unroll
      for (int nt = 0; nt < 8; nt++) {
        mx0 = fmaxf(mx0, fmaxf(sc[mt][nt][0], sc[mt][nt][1]));
        mx1 = fmaxf(mx1, fmaxf(sc[mt][nt][2], sc[mt][nt][3]));
      }
      mx0 = fmaxf(mx0, __shfl_xor_sync(0xffffffffu, mx0, 1));
      mx0 = fmaxf(mx0, __shfl_xor_sync(0xffffffffu, mx0, 2));
      mx1 = fmaxf(mx1, __shfl_xor_sync(0xffffffffu, mx1, 1));
      mx1 = fmaxf(mx1, __shfl_xor_sync(0xffffffffu, mx1, 2));

      float mn0 = fmaxf(mrow[mt][0], mx0);
      float mn1 = fmaxf(mrow[mt][1], mx1);
      float e0 = fexp2(mrow[mt][0] - mn0);
      float e1 = fexp2(mrow[mt][1] - mn1);
      mrow[mt][0] = mn0; mrow[mt][1] = mn1;

      float s0 = 0.f, s1 = 0.f;
      uint32_t* pr0 = Ps32 + (wq0 + mt * 16 + lr8) * (LD / 2) + lq;
      uint32_t* pr1 = pr0 + 8 * (LD / 2);
#pragma unroll
      for (int nt = 0; nt < 8; nt++) {
        float p0 = fexp2(sc[mt][nt][0] - mn0);
        float p1 = fexp2(sc[mt][nt][1] - mn0);
        float p2 = fexp2(sc[mt][nt][2] - mn1);
        float p3 = fexp2(sc[mt][nt][3] - mn1);
        uint32_t h01 = pack_h2(p0, p1);
        uint32_t h23 = pack_h2(p2, p3);
        // sum the fp16-rounded values so normalizer matches PV inputs
        __half2 r01 = *(__half2*)&h01, r23 = *(__half2*)&h23;
        s0 += __low2float(r01) + __high2float(r01);
        s1 += __low2float(r23) + __high2float(r23);
        pr0[nt * 4] = h01;
        pr1[nt * 4] = h23;
      }
      s0 += __shfl_xor_sync(0xffffffffu, s0, 1);
      s0 += __shfl_xor_sync(0xffffffffu, s0, 2);
      s1 += __shfl_xor_sync(0xffffffffu, s1, 1);
      s1 += __shfl_xor_sync(0xffffffffu, s1, 2);
      lrow[mt][0] = lrow[mt][0] * e0 + s0;
      lrow[mt][1] = lrow[mt][1] * e1 + s1;
#pragma unroll
      for (int nt = 0; nt < 8; nt++) {
        out[mt][nt][0] *= e0; out[mt][nt][1] *= e0;
        out[mt][nt][2] *= e1; out[mt][nt][3] *= e1;
      }
    }
    __syncwarp();

    // out += P V   (k = key positions, 64 -> 4 k16 steps; V transposed [d][k])
#pragma unroll
    for (int ks = 0; ks < 4; ks++) {
      const int kh = ks * 8;
      uint32_t af[2][4], bf[8][2];
#pragma unroll
      for (int mt = 0; mt < 2; mt++) {
        const uint32_t* ap = Ps32 + (wq0 + mt * 16 + lr8) * (LD / 2) + kh + lq;
        af[mt][0] = ap[0];
        af[mt][1] = ap[8 * (LD / 2)];
        af[mt][2] = ap[4];
        af[mt][3] = ap[8 * (LD / 2) + 4];
      }
#pragma unroll
      for (int nt = 0; nt < 8; nt++) {
        const uint32_t* bp = Vs32 + (nt * 8 + lr8) * (LD / 2) + kh + lq;
        bf[nt][0] = bp[0];
        bf[nt][1] = bp[4];
      }
#pragma unroll
      for (int mt = 0; mt < 2; mt++)
#pragma unroll
        for (int nt = 0; nt < 8; nt++) mma_f16(out[mt][nt], af[mt], bf[nt]);
    }
    __syncthreads();
    if (kt + 1 < nkt) issue_V(k0 + 64);
  }

  // Epilogue: normalize, store ctx as fp16 ([b*s, 2048] for O-proj)
  __half* Cb = Ctx + (long)(b * kS + q0) * kDout + h * kHD;
#pragma unroll
  for (int mt = 0; mt < 2; mt++) {
    int r0 = wq0 + mt * 16 + lr8;
    float inv0 = 1.f / lrow[mt][0];
    float inv1 = 1.f / lrow[mt][1];
#pragma unroll
    for (int nt = 0; nt < 8; nt++) {
      int col = nt * 8 + 2 * lq;
      *(uint32_t*)(Cb + (long)r0 * kDout + col) =
          pack_h2(out[mt][nt][0] * inv0, out[mt][nt][1] * inv0);
      *(uint32_t*)(Cb + (long)(r0 + 8) * kDout + col) =
          pack_h2(out[mt][nt][2] * inv1, out[mt][nt][3] * inv1);
    }
  }
}

// ---------------------------------------------------------------------------
extern "C" void kernel_launch(void* const* d_in, const int* in_sizes, int n_in,
                              void* d_out, int out_size) {
  const float* x  = (const float*)d_in[0];
  const float* Wq = (const float*)d_in[1];
  const float* Wk = (const float*)d_in[2];
  const float* Wv = (const float*)d_in[3];
  const float* Wo = (const float*)d_in[4];

  float* out    = (float*)d_out;                    // [2,2048,2048]
  float* keys   = out + kM * kDout;                 // [2,8,2048,64]
  float* values = keys + kB * kNKV * kS * kHD;      // [2,8,2048,64]

  __half *qb, *kh, *vh, *cb, *xh, *wqh, *wkh, *wvh, *woh;
  cudaGetSymbolAddress((void**)&qb, g_Q);
  cudaGetSymbolAddress((void**)&kh, g_Kh);
  cudaGetSymbolAddress((void**)&vh, g_Vh);
  cudaGetSymbolAddress((void**)&cb, g_Ctx);
  cudaGetSymbolAddress((void**)&xh, g_xh);
  cudaGetSymbolAddress((void**)&wqh, g_Wqh);
  cudaGetSymbolAddress((void**)&wkh, g_Wkh);
  cudaGetSymbolAddress((void**)&wvh, g_Wvh);
  cudaGetSymbolAddress((void**)&woh, g_Woh);

  constexpr int kGemmSmem = 2 * 2 * 128 * 40 * (int)sizeof(__half);   // 40960 B
  constexpr int kAttnSmem = (128 + 64 + 64 + 128) * 72 * (int)sizeof(__half);  // 55296 B
  static bool attr_set = false;
  if (!attr_set) {
    cudaFuncSetAttribute(proj_qkv, cudaFuncAttributeMaxDynamicSharedMemorySize, kGemmSmem);
    cudaFuncSetAttribute(gemm_out, cudaFuncAttributeMaxDynamicSharedMemorySize, kGemmSmem);
    cudaFuncSetAttribute(attn_f16, cudaFuncAttributeMaxDynamicSharedMemorySize, kAttnSmem);
    attr_set = true;
  }

  // 0. Cast all GEMM operands to fp16
  constexpr int n0 = kM * kDin / 4;      // x
  constexpr int n1 = kDout * kDin / 4;   // Wq
  constexpr int n2 = kKV * kDin / 4;     // Wk
  constexpr int n3 = kKV * kDin / 4;     // Wv
  constexpr int n4 = kDin * kDout / 4;   // Wo
  constexpr int ntot = n0 + n1 + n2 + n3 + n4;
  half5<<<(ntot + 255) / 256, 256>>>(
      (const float4*)x,  (uint2*)xh,  n0,
      (const float4*)Wq, (uint2*)wqh, n1,
      (const float4*)Wk, (uint2*)wkh, n2,
      (const float4*)Wv, (uint2*)wvh, n3,
      (const float4*)Wo, (uint2*)woh, n4);

  // 1. Fused Q/K/V projections
  proj_qkv<<<dim3(24, kM / 128), 256, kGemmSmem>>>(
      xh, wqh, wkh, wvh, qb, keys, values, kh, vh);
  // 2. Attention (fp16 tensor cores, cp.async pipelined)
  attn_f16<<<dim3(kS / 128, kB * kNH), dim3(128), kAttnSmem>>>(qb, kh, vh, cb);
  // 3. Output projection
  gemm_out<<<dim3(kDout / 128, kM / 128), 256, kGemmSmem>>>(cb, woh, out, kDout, kDin);
}